// round 12
// baseline (speedup 1.0000x reference)
#include <cuda_runtime.h>
#include <cuda_bf16.h>

#define ROWS       4096
#define COLS_TOT   50001
#define COLS       50000
#define NTHREADS   512
#define NLOG_LOW   9.210340371976184f   /* -log(1e-4) */
#define P_EPS      1e-7f

// Self-resetting accumulator: zero-initialized at module load; the last CTA of
// each launch writes out[0] and restores both to zero, so every graph replay
// starts from the same state. Single kernel launch, no init kernel needed.
__device__ float        g_acc   = 0.0f;
__device__ unsigned int g_count = 0u;

// One CTA per row. Single HBM pass: s = sum(exp(x)) over the first 50000 cols;
// lse = log(s); row value = (lse - x_lab) + NLOG_LOW*(1 - p_true).
__global__ __launch_bounds__(NTHREADS) void sce_row_kernel(
    const float* __restrict__ pred,
    const int*   __restrict__ labels32,   // may actually be int64; sniffed below
    float*       __restrict__ out)
{
    const int row = blockIdx.x;
    const int tid = threadIdx.x;
    const size_t base = (size_t)row * COLS_TOT;
    const float* p = pred + base;

    // ---- Prefetch the label-dependent chain BEFORE the streaming loop so its
    // ~3 dependent DRAM loads overlap with the 200 KB stream (tid 0 only).
    float x_lab = 0.0f;
    if (tid == 0) {
        // dtype sniff: if labels are int64, every odd int32 word is 0
        // (labels in [0, 50000)). P(false positive for int32 data) ~ (2e-5)^16.
        int acc = 0;
        #pragma unroll
        for (int i = 0; i < 16; i++) acc |= labels32[2 * i + 1];
        const int lab = (acc == 0) ? (int)((const long long*)labels32)[row]
                                   : labels32[row];
        x_lab = __ldg(p + lab);
    }

    // Row base alignment: base % 4 == row % 4 elements. Peel to 16B alignment.
    const int mis  = (int)(base & 3);
    const int peel = (4 - mis) & 3;
    const int nvec = (COLS - peel) >> 2;
    const int tail = (COLS - peel) & 3;

    float s0 = 0.0f, s1 = 0.0f, s2 = 0.0f, s3 = 0.0f;
    if (tid < peel) s0 += __expf(p[tid]);

    // Streaming (evict-first) 16B loads: data is read exactly once.
    const float4* __restrict__ v = (const float4*)(p + peel);
    #pragma unroll 8
    for (int i = tid; i < nvec; i += NTHREADS) {
        float4 x = __ldcs(v + i);
        s0 += __expf(x.x);
        s1 += __expf(x.y);
        s2 += __expf(x.z);
        s3 += __expf(x.w);
    }
    if (tid < tail) s1 += __expf(p[peel + (nvec << 2) + tid]);

    float s = (s0 + s2) + (s1 + s3);

    // Block reduce (16 warps)
    __shared__ float warp_s[16];
    #pragma unroll
    for (int o = 16; o; o >>= 1) s += __shfl_xor_sync(0xffffffffu, s, o);
    if ((tid & 31) == 0) warp_s[tid >> 5] = s;
    __syncthreads();

    if (tid < 32) {
        float t = (tid < 16) ? warp_s[tid] : 0.0f;
        #pragma unroll
        for (int o = 8; o; o >>= 1) t += __shfl_xor_sync(0xffffffffu, t, o);

        if (tid == 0) {
            float lse = logf(t);

            float p_true = __expf(x_lab - lse);
            p_true = fminf(fmaxf(p_true, P_EPS), 1.0f);

            // sum(p) == 1 analytically (clip correction < 1e-7 here)
            float val = (lse - x_lab) + NLOG_LOW * (1.0f - p_true);

            atomicAdd(&g_acc, val * (1.0f / (float)ROWS));
            __threadfence();
            unsigned int old = atomicAdd(&g_count, 1u);
            if (old == (unsigned)(ROWS - 1)) {
                // All CTAs' adds are visible (each fenced before its count).
                float total = atomicAdd(&g_acc, 0.0f);   // coherent read
                out[0] = total;
                // Self-reset for the next graph replay.
                atomicExch(&g_acc, 0.0f);
                atomicExch(&g_count, 0u);
            }
        }
    }
}

extern "C" void kernel_launch(void* const* d_in, const int* in_sizes, int n_in,
                              void* d_out, int out_size)
{
    const float* pred   = (const float*)d_in[0];
    const int*   labels = (const int*)d_in[1];
    float*       out    = (float*)d_out;

    sce_row_kernel<<<ROWS, NTHREADS>>>(pred, labels, out);
}